// round 2
// baseline (speedup 1.0000x reference)
#include <cuda_runtime.h>

// HashEncoder: D=3, L=16, C=2, BASE=16, PLS=2, T=2^19, B=2^21
// Levels 0..2 dense (res^3 <= T), levels 3..15 hashed into T=524288 entries.
// Output: [B, 32] float32, level-major channel pairs.

#define NPOINTS  2097152
#define NLEV     16
#define TSIZE    524288u
#define HMASK    524287u
#define PRIME1   2654435761u
#define PRIME2   805459861u
#define BLOCK    256

// Row offsets into the embedding table (rows of 2 floats) per level.
// l0:16^3=4096 dense, l1:32^3=32768 dense, l2:64^3=262144 dense, l3..15: T each.
__device__ static constexpr int OFFS[16] = {
    0, 4096, 36864, 299008,
    823296, 1347584, 1871872, 2396160,
    2920448, 3444736, 3969024, 4493312,
    5017600, 5541888, 6066176, 6590464
};

__global__ void __launch_bounds__(BLOCK)
hash_encode_kernel(const float* __restrict__ in,
                   const float* __restrict__ emb,
                   float* __restrict__ out)
{
    // 33-float pitch to avoid smem bank conflicts on the transpose.
    __shared__ float s_out[BLOCK * 33];

    const int tid = threadIdx.x;
    const long long p = (long long)blockIdx.x * BLOCK + tid;

    const float x = in[p * 3 + 0];
    const float y = in[p * 3 + 1];
    const float z = in[p * 3 + 2];

    float acc[2 * NLEV];

#pragma unroll
    for (int l = 0; l < NLEV; l++) {
        const int res = 16 << l;                     // exact: ceil(16*2^l)
        const float scale = (float)(res - 1);

        const float px = x * scale;
        const float py = y * scale;
        const float pz = z * scale;

        int ix0 = __float2int_rd(px);
        int iy0 = __float2int_rd(py);
        int iz0 = __float2int_rd(pz);

        const float fx = px - (float)ix0;
        const float fy = py - (float)iy0;
        const float fz = pz - (float)iz0;

        // inputs are in [0,1] so lower clamp is a no-op; clamp upper corner.
        const int ix1 = min(ix0 + 1, res - 1);
        const int iy1 = min(iy0 + 1, res - 1);
        const int iz1 = min(iz0 + 1, res - 1);

        const float wx[2]  = {1.0f - fx, fx};
        const float wyz[4] = {(1.0f - fy) * (1.0f - fz),
                              fy * (1.0f - fz),
                              (1.0f - fy) * fz,
                              fy * fz};

        const float2* __restrict__ e = (const float2*)emb + OFFS[l];

        float r0 = 0.0f, r1 = 0.0f;

        const bool dense = ((long long)res * res * res) <= (long long)TSIZE; // compile-time

        unsigned xs[2];
        unsigned yz[4];
        if (dense) {
            const unsigned r = (unsigned)res;
            const unsigned r2 = r * r;
            xs[0] = (unsigned)ix0;
            xs[1] = (unsigned)ix1;
            yz[0] = (unsigned)iy0 * r + (unsigned)iz0 * r2;
            yz[1] = (unsigned)iy1 * r + (unsigned)iz0 * r2;
            yz[2] = (unsigned)iy0 * r + (unsigned)iz1 * r2;
            yz[3] = (unsigned)iy1 * r + (unsigned)iz1 * r2;
        } else {
            xs[0] = (unsigned)ix0;                  // PRIMES[0] == 1
            xs[1] = (unsigned)ix1;
            const unsigned hy0 = (unsigned)iy0 * PRIME1;
            const unsigned hy1 = (unsigned)iy1 * PRIME1;
            const unsigned hz0 = (unsigned)iz0 * PRIME2;
            const unsigned hz1 = (unsigned)iz1 * PRIME2;
            yz[0] = hy0 ^ hz0;
            yz[1] = hy1 ^ hz0;
            yz[2] = hy0 ^ hz1;
            yz[3] = hy1 ^ hz1;
        }

#pragma unroll
        for (int cyz = 0; cyz < 4; cyz++) {
#pragma unroll
            for (int cx = 0; cx < 2; cx++) {
                unsigned idx;
                if (dense) idx = xs[cx] + yz[cyz];
                else       idx = (xs[cx] ^ yz[cyz]) & HMASK;
                const float w = wx[cx] * wyz[cyz];
                const float2 v = __ldg(&e[idx]);
                r0 = fmaf(w, v.x, r0);
                r1 = fmaf(w, v.y, r1);
            }
        }

        acc[2 * l + 0] = r0;
        acc[2 * l + 1] = r1;
    }

    // Stage to smem, then store the block's [256 x 32] tile fully coalesced.
#pragma unroll
    for (int j = 0; j < 32; j++)
        s_out[tid * 33 + j] = acc[j];
    __syncthreads();

    float* __restrict__ out_blk = out + (long long)blockIdx.x * BLOCK * 32;
#pragma unroll
    for (int i = tid; i < BLOCK * 32; i += BLOCK) {
        const int pp = i >> 5;
        const int ee = i & 31;
        out_blk[i] = s_out[pp * 33 + ee];
    }
}

extern "C" void kernel_launch(void* const* d_in, const int* in_sizes, int n_in,
                              void* d_out, int out_size)
{
    const float* in  = (const float*)d_in[0];   // [B,3] float32
    const float* emb = (const float*)d_in[1];   // [TOTAL_PARAMS,2] float32
    float* out = (float*)d_out;                 // [B,32] float32

    hash_encode_kernel<<<NPOINTS / BLOCK, BLOCK>>>(in, emb, out);
}